// round 7
// baseline (speedup 1.0000x reference)
#include <cuda_runtime.h>

#define BATCH 1024
#define FDIM 32
#define EMBED 8
#define HEADS 4
#define NBINS 1100
#define OUTD 16
#define FH (FDIM*HEADS)

typedef unsigned long long u64;

// Scratch (allocation-free: __device__ globals)
__device__ float2 g_q[FH * BATCH];
__device__ float2 g_k[FH * BATCH];
__device__ float2 g_v[FH * BATCH];
__device__ float g_o[BATCH * FDIM * EMBED];   // [B][256]

// ---- packed f32x2 helpers (Blackwell FFMA2 path, PTX-only) -----------------
__device__ __forceinline__ u64 pk(float lo, float hi) {
    u64 r; asm("mov.b64 %0, {%1, %2};" : "=l"(r) : "f"(lo), "f"(hi)); return r;
}
__device__ __forceinline__ void upk(u64 a, float& x, float& y) {
    asm("mov.b64 {%0, %1}, %2;" : "=f"(x), "=f"(y) : "l"(a));
}
__device__ __forceinline__ u64 fma2(u64 a, u64 b, u64 c) {
    u64 d; asm("fma.rn.f32x2 %0, %1, %2, %3;" : "=l"(d) : "l"(a), "l"(b), "l"(c)); return d;
}
__device__ __forceinline__ u64 mul2(u64 a, u64 b) {
    u64 d; asm("mul.rn.f32x2 %0, %1, %2;" : "=l"(d) : "l"(a), "l"(b)); return d;
}
__device__ __forceinline__ u64 add2(u64 a, u64 b) {
    u64 d; asm("add.rn.f32x2 %0, %1, %2;" : "=l"(d) : "l"(a), "l"(b)); return d;
}
__device__ __forceinline__ float ex2f(float s) {
    float e; asm("ex2.approx.ftz.f32 %0, %1;" : "=f"(e) : "f"(s)); return e;
}

// Packed exp2 on the FMA pipe: 8 packed FMA-pipe ops + 4 ALU ops per 2 exps.
__device__ __forceinline__ u64 exp2_poly2(u64 x) {
    const float MAGIC = 12582912.0f;            // 2^23 + 2^22
    u64 t = add2(x, pk(MAGIC, MAGIC));          // n captured in mantissa
    u64 u = add2(t, pk(-MAGIC, -MAGIC));        // u = round(x)
    u64 r = fma2(u, pk(-1.0f, -1.0f), x);       // r = x - u, |r| <= 0.5
    u64 p = fma2(pk(0.00961813f, 0.00961813f), r, pk(0.05550411f, 0.05550411f));
    p = fma2(p, r, pk(0.24022651f, 0.24022651f));
    p = fma2(p, r, pk(0.69314718f, 0.69314718f));
    p = fma2(p, r, pk(1.0f, 1.0f));
    float tlo, thi; upk(t, tlo, thi);
    unsigned ilo = (__float_as_uint(tlo) << 23) + (127u << 23);   // bits of 2^n_lo
    unsigned ihi = (__float_as_uint(thi) << 23) + (127u << 23);
    return mul2(p, pk(__uint_as_float(ilo), __uint_as_float(ihi)));
}

// Replicate jnp.linspace(MN,MX,NBINS) element: step*i + start, fp32 rounding
// at each op (no FMA contraction).
__device__ __forceinline__ float binv(int i) {
    const float step = 301.0f / 1099.0f;
    return __fadd_rn(__fmul_rn(step, (float)i), -1.0f);
}

// ---------------------------------------------------------------------------
// Stage A: bin search + embedding gather + QKV projection, per-HEAD threads.
// grid (16, 32) x 256: tid -> h = tid>>6 (warp-uniform), b = base + (tid&63).
// Each thread: 1 gather (L1-shared across the 4 h-copies), 6 rows x 8 FMA,
// 3 coalesced STG.64. 131K threads for latency hiding.
// ---------------------------------------------------------------------------
__global__ void stageA(const float* __restrict__ x, const float* __restrict__ emb,
                       const float* __restrict__ ipw, const float* __restrict__ ipb) {
    __shared__ float sw[192];
    __shared__ float sb[24];
    int tid = threadIdx.x;
    if (tid < 192) sw[tid] = ipw[tid];
    if (tid < 24)  sb[tid] = ipb[tid];
    __syncthreads();

    int f = blockIdx.y;
    int h = tid >> 6;                       // warp-uniform
    int b = blockIdx.x * 64 + (tid & 63);

    float xv = x[b * FDIM + f];
    float xc = fminf(fmaxf(xv, -1.0f), 300.0f);

    // searchsorted(bins, xc, 'left'): first i with bins[i] >= xc
    int i = (int)((xc + 1.0f) * (1099.0f / 301.0f));
    i = max(0, min(i, NBINS - 1));
    while (i > 0 && binv(i - 1) >= xc) --i;
    while (i < NBINS - 1 && binv(i) < xc) ++i;

    const float4* ep = (const float4*)(emb + ((size_t)f * NBINS + i) * EMBED);
    float4 e0 = ep[0], e1 = ep[1];
    float xe[8] = {e0.x, e0.y, e0.z, e0.w, e1.x, e1.y, e1.z, e1.w};

    // only this head's 6 rows: q{2h,2h+1} k{8+2h,9+2h} v{16+2h,17+2h}
    float rr[6];
    int rows[6] = {2*h, 2*h + 1, 8 + 2*h, 9 + 2*h, 16 + 2*h, 17 + 2*h};
#pragma unroll
    for (int r6 = 0; r6 < 6; ++r6) {
        int r = rows[r6];
        float acc = sb[r];
#pragma unroll
        for (int j = 0; j < 8; ++j) acc = fmaf(xe[j], sw[r * 8 + j], acc);
        rr[r6] = acc;
    }

    int o = (f * HEADS + h) * BATCH + b;
    g_q[o] = make_float2(rr[0], rr[1]);
    g_k[o] = make_float2(rr[2], rr[3]);
    g_v[o] = make_float2(rr[4], rr[5]);
}

// ---------------------------------------------------------------------------
// Stage B: per-(f,h) attention over batch axis, hd=2, single-pass softmax.
// (unchanged from R6 -- measured best; MUFU/issue co-bound near floor)
// ---------------------------------------------------------------------------
__global__ void stageB() {
    __shared__ ulonglong2 sA[BATCH / 2];   // 8KB
    __shared__ ulonglong2 sB[BATCH / 2];   // 8KB
    int fh  = blockIdx.x;
    int tid = threadIdx.x;

    const float4* kp = (const float4*)(g_k + fh * BATCH);  // (k0e,k1e,k0o,k1o)
    const float4* vp = (const float4*)(g_v + fh * BATCH);
    for (int p = tid; p < BATCH / 2; p += 128) {
        float4 k = kp[p];
        float4 v = vp[p];
        sA[p] = make_ulonglong2(pk(k.x, k.z), pk(k.y, k.w));
        sB[p] = make_ulonglong2(pk(v.x, v.z), pk(v.y, v.w));
    }
    __syncthreads();

    int b = blockIdx.y * 128 + tid;
    float2 q = g_q[fh * BATCH + b];
    const float C = 1.4426950408889634f * 0.70710678118654752f;
    float q0 = q.x * C, q1 = q.y * C;
    u64 qq0 = pk(q0, q0), qq1 = pk(q1, q1);
    u64 dd = pk(0.f, 0.f), aa0 = dd, aa1 = dd;

    for (int pb = 0; pb < BATCH / 2; pb += 8) {
        {
            ulonglong2 A  = sA[pb];
            ulonglong2 Bv = sB[pb];
            u64 ee = exp2_poly2(fma2(qq0, A.x, mul2(qq1, A.y)));
            dd  = add2(dd, ee);
            aa0 = fma2(ee, Bv.x, aa0);
            aa1 = fma2(ee, Bv.y, aa1);
        }
#pragma unroll
        for (int j = 1; j < 8; ++j) {
            ulonglong2 A  = sA[pb + j];
            ulonglong2 Bv = sB[pb + j];
            u64 ss = fma2(qq0, A.x, mul2(qq1, A.y));
            float s0, s1; upk(ss, s0, s1);
            u64 ee = pk(ex2f(s0), ex2f(s1));
            dd  = add2(dd, ee);
            aa0 = fma2(ee, Bv.x, aa0);
            aa1 = fma2(ee, Bv.y, aa1);
        }
    }

    float d0, d1, a00, a01, a10, a11;
    upk(dd, d0, d1); upk(aa0, a00, a01); upk(aa1, a10, a11);
    float inv = 1.0f / (d0 + d1);
    int f = fh >> 2, h = fh & 3;
    float* op = g_o + (size_t)b * (FDIM * EMBED) + f * EMBED + h * 2;
    op[0] = (a00 + a01) * inv;
    op[1] = (a10 + a11) * inv;
}

// ---------------------------------------------------------------------------
// Stage C: out_proj (8x8 per f) + linear (16x256) + softmax(16)
// grid 128 x 256 threads : one warp per batch row, lane = f
// ---------------------------------------------------------------------------
__global__ void stageC(const float* __restrict__ opw, const float* __restrict__ opb,
                       const float* __restrict__ lw,  const float* __restrict__ lb,
                       float* __restrict__ out) {
    __shared__ float sWo[64];
    __shared__ float sbo[8];
    __shared__ float sLw[256 * 16];     // transposed: [i][t]
    __shared__ float sLb[16];
    __shared__ float o2sh[8][256];      // one 256-vector per warp

    int tid = threadIdx.x;
    for (int idx = tid; idx < 256 * 16; idx += blockDim.x) {
        int i = idx >> 4, t = idx & 15;
        sLw[idx] = lw[t * 256 + i];
    }
    if (tid < 64) sWo[tid] = opw[tid];
    if (tid < 8)  sbo[tid] = opb[tid];
    if (tid < 16) sLb[tid] = lb[tid];
    __syncthreads();

    int w = tid >> 5, lane = tid & 31;
    int b = blockIdx.x * 8 + w;

    // lane l owns feature f = l
    const float4* op = (const float4*)(g_o + (size_t)b * 256 + lane * 8);
    float4 v0 = op[0], v1 = op[1];
    float o[8] = {v0.x, v0.y, v0.z, v0.w, v1.x, v1.y, v1.z, v1.w};

#pragma unroll
    for (int e = 0; e < 8; ++e) {
        float acc = sbo[e];
#pragma unroll
        for (int j = 0; j < 8; ++j) acc = fmaf(o[j], sWo[e * 8 + j], acc);
        o2sh[w][lane * 8 + e] = acc;
    }
    __syncwarp();

    if (lane < 16) {
        float acc = sLb[lane];
#pragma unroll 8
        for (int i = 0; i < 256; ++i)
            acc = fmaf(o2sh[w][i], sLw[i * 16 + lane], acc);

        // softmax over 16 lanes
        float m = acc;
#pragma unroll
        for (int off = 8; off; off >>= 1)
            m = fmaxf(m, __shfl_xor_sync(0xffffu, m, off, 16));
        float e = __expf(acc - m);
        float s = e;
#pragma unroll
        for (int off = 8; off; off >>= 1)
            s += __shfl_xor_sync(0xffffu, s, off, 16);
        out[b * OUTD + lane] = e / s;
    }
}

// ---------------------------------------------------------------------------
extern "C" void kernel_launch(void* const* d_in, const int* in_sizes, int n_in,
                              void* d_out, int out_size) {
    const float* x   = (const float*)d_in[0];   // (1024, 32)
    const float* emb = (const float*)d_in[1];   // (32, 1100, 8)
    const float* ipw = (const float*)d_in[2];   // (24, 8)
    const float* ipb = (const float*)d_in[3];   // (24,)
    const float* opw = (const float*)d_in[4];   // (8, 8)
    const float* opb = (const float*)d_in[5];   // (8,)
    const float* lw  = (const float*)d_in[6];   // (16, 256)
    const float* lb  = (const float*)d_in[7];   // (16,)
    float* out = (float*)d_out;                 // (1024, 16)

    stageA<<<dim3(16, FDIM), 256>>>(x, emb, ipw, ipb);
    stageB<<<dim3(FH, BATCH / 128), 128>>>();
    stageC<<<BATCH / 8, 256>>>(opw, opb, lw, lb, out);
}